// round 7
// baseline (speedup 1.0000x reference)
#include <cuda_runtime.h>
#include <cuda_bf16.h>
#include <cstdint>

#define Bb 4096
#define Nn 256
#define Dd 64
#define Cc 3
#define Mm 32

typedef unsigned long long ull;

#define OUT_XI_OFF ((size_t)Bb * Dd)
#define OUT_HJ_OFF (OUT_XI_OFF + (size_t)Bb * Cc)
#define OUT_XJ_OFF (OUT_HJ_OFF + (size_t)Bb * Nn * Dd)

// ---- dynamic smem layout (byte offsets from 1024-aligned base) ----
#define SMO_A_HI  0        // 256 x 64 bf16 = 32768, SW128 swizzled
#define SMO_A_LO  32768    // 32768
#define SMO_BFRAG 65536    // Blo frags: 16 x 32 x 8B = 4096
#define SMO_WH    69632    // 96 x 64 fp32 = 24576
#define SMO_WEHI  94208    // 64 x 32 fp32 = 8192
#define SMO_XJ    102400   // 768 fp32 = 3072
#define SMO_HI    105472   // 2 x 64 fp32 = 512 (double buffered)
#define SMO_BASEC 105984   // 32 x float4 = 512
#define SMO_BE    106496   // 32 fp32
#define SMO_WX2   106624   // 32 fp32
#define SMO_MIP   106752   // 8 x 32 fp32 = 1024
#define SMO_XA    107776   // 8 x 4 fp32
#define SMO_MIF   107904   // 32 fp32
#define SMO_XIV   108032   // 2 x 4 fp32 (double buffered)
#define SMO_SC    108064   // bx, bx2
#define SMEM_TOTAL (108072 + 1024)

__device__ __forceinline__ uint32_t smem_u32(const void* p) {
    uint32_t a;
    asm("{ .reg .u64 t; cvta.to.shared.u64 t, %1; cvt.u32.u64 %0, t; }" : "=r"(a) : "l"(p));
    return a;
}
__device__ __forceinline__ uint32_t swz(uint32_t byte) {
    return byte ^ ((byte >> 3) & 0x70);
}
__device__ __forceinline__ float silu_f(float x) {
    float e, r;
    asm("ex2.approx.f32 %0, %1;" : "=f"(e) : "f"(x * -1.442695041f));
    asm("rcp.approx.f32 %0, %1;" : "=f"(r) : "f"(e + 1.0f));
    return x * r;
}
__device__ __forceinline__ uint32_t pack_bf16(float lo, float hi) {
    __nv_bfloat162 t = __float22bfloat162_rn(make_float2(lo, hi));
    return *(uint32_t*)&t;
}
__device__ __forceinline__ void ldm_x4(uint32_t& a0, uint32_t& a1,
                                       uint32_t& a2, uint32_t& a3, uint32_t addr) {
    asm volatile("ldmatrix.sync.aligned.m8n8.x4.shared.b16 {%0,%1,%2,%3}, [%4];"
                 : "=r"(a0), "=r"(a1), "=r"(a2), "=r"(a3) : "r"(addr));
}
__device__ __forceinline__ void mma_bf16(float* c, uint32_t a0, uint32_t a1,
                                         uint32_t a2, uint32_t a3,
                                         uint32_t b0, uint32_t b1) {
    asm volatile(
        "mma.sync.aligned.m16n8k16.row.col.f32.bf16.bf16.f32 "
        "{%0,%1,%2,%3}, {%4,%5,%6,%7}, {%8,%9}, {%0,%1,%2,%3};"
        : "+f"(c[0]), "+f"(c[1]), "+f"(c[2]), "+f"(c[3])
        : "r"(a0), "r"(a1), "r"(a2), "r"(a3), "r"(b0), "r"(b1));
}
// stage one float4 of hj: pass-through STG + split-bf16 (trunc hi / residual lo) STS
__device__ __forceinline__ void split_sts(char* sm, int g, float4 v, float4* o4) {
    o4[g] = v;
    int row = g >> 4, grp = g & 15;
    uint32_t off = swz((uint32_t)(row * 128 + grp * 8));
    uint32_t ux = __float_as_uint(v.x), uy = __float_as_uint(v.y);
    uint32_t uz = __float_as_uint(v.z), uw = __float_as_uint(v.w);
    uint32_t ph0 = __byte_perm(ux, uy, 0x7632);   // [hi16(x) | hi16(y)]
    uint32_t ph1 = __byte_perm(uz, uw, 0x7632);
    float lx = v.x - __uint_as_float(ux & 0xFFFF0000u);
    float ly = v.y - __uint_as_float(uy & 0xFFFF0000u);
    float lz = v.z - __uint_as_float(uz & 0xFFFF0000u);
    float lw = v.w - __uint_as_float(uw & 0xFFFF0000u);
    uint32_t pl0 = pack_bf16(lx, ly), pl1 = pack_bf16(lz, lw);
    *(ull*)(sm + SMO_A_HI + off) = (ull)ph0 | ((ull)ph1 << 32);
    *(ull*)(sm + SMO_A_LO + off) = (ull)pl0 | ((ull)pl1 << 32);
}

__global__ __launch_bounds__(256, 2) void e2gn2_kernel(
    const float* __restrict__ hi, const float* __restrict__ xi,
    const float* __restrict__ hj, const float* __restrict__ xj,
    const float* __restrict__ We, const float* __restrict__ be,
    const float* __restrict__ Wx, const float* __restrict__ bx,
    const float* __restrict__ Wx2, const float* __restrict__ bx2,
    const float* __restrict__ Wh, const float* __restrict__ bh,
    float* __restrict__ out)
{
    extern __shared__ char raw_sm[];
    char* sm = (char*)(((uintptr_t)raw_sm + 1023) & ~(uintptr_t)1023);

    const int tid  = threadIdx.x;
    const int w    = tid >> 5;
    const int lane = tid & 31;
    const int q    = lane >> 2;
    const int s    = lane & 3;

    float*  smWh   = (float*)(sm + SMO_WH);
    float*  smWeHi = (float*)(sm + SMO_WEHI);
    float*  smXj   = (float*)(sm + SMO_XJ);
    float*  smHi   = (float*)(sm + SMO_HI);     // [2][64]
    float4* smBaseC= (float4*)(sm + SMO_BASEC);
    float*  smBe   = (float*)(sm + SMO_BE);
    float*  smWx2  = (float*)(sm + SMO_WX2);
    float*  smMip  = (float*)(sm + SMO_MIP);
    float*  smXa   = (float*)(sm + SMO_XA);
    float*  smMif  = (float*)(sm + SMO_MIF);
    float*  smXiV  = (float*)(sm + SMO_XIV);    // [2][4]
    float*  smSc   = (float*)(sm + SMO_SC);
    uint32_t* smBfrag = (uint32_t*)(sm + SMO_BFRAG);

    const uint32_t aHiAddr = smem_u32(sm + SMO_A_HI);
    const uint32_t aLoAddr = smem_u32(sm + SMO_A_LO);

    // ================= one-time init =================
    if (tid == 0) { smSc[0] = bx[0]; smSc[1] = bx2[0]; }
    if (tid < 32) { smBe[tid] = be[tid]; smWx2[tid] = Wx2[tid]; }
    for (int i = tid; i < 2048; i += 256) smWeHi[i] = We[i];
    for (int i = tid; i < 6144; i += 256) smWh[i] = Wh[i];

    uint32_t BH0[4][4], BH1[4][4];
    {
        const int nb = (lane >> 2);
        const int kb = (lane & 3) * 2;
        #pragma unroll
        for (int kk = 0; kk < 4; kk++) {
            #pragma unroll
            for (int nt = 0; nt < 4; nt++) {
                const int n  = nt * 8 + nb;
                const int k0 = kk * 16 + kb;
                float v0 = We[(Dd + k0    ) * Mm + n];
                float v1 = We[(Dd + k0 + 1) * Mm + n];
                float v2 = We[(Dd + k0 + 8) * Mm + n];
                float v3 = We[(Dd + k0 + 9) * Mm + n];
                __nv_bfloat16 h0 = __float2bfloat16(v0), h1 = __float2bfloat16(v1);
                __nv_bfloat16 h2 = __float2bfloat16(v2), h3 = __float2bfloat16(v3);
                BH0[kk][nt] = ((uint32_t)*(unsigned short*)&h1 << 16) | *(unsigned short*)&h0;
                BH1[kk][nt] = ((uint32_t)*(unsigned short*)&h3 << 16) | *(unsigned short*)&h2;
                if (w == 0) {
                    float l0 = v0 - __bfloat162float(h0), l1 = v1 - __bfloat162float(h1);
                    float l2 = v2 - __bfloat162float(h2), l3 = v3 - __bfloat162float(h3);
                    smBfrag[((kk * 4 + nt) * 32 + lane) * 2 + 0] = pack_bf16(l0, l1);
                    smBfrag[((kk * 4 + nt) * 32 + lane) * 2 + 1] = pack_bf16(l2, l3);
                }
            }
        }
    }
    float wxr_[8];
    #pragma unroll
    for (int nt = 0; nt < 4; nt++) {
        wxr_[nt * 2 + 0] = Wx[nt * 8 + 2 * s + 0];
        wxr_[nt * 2 + 1] = Wx[nt * 8 + 2 * s + 1];
    }
    const float bxv  = bx[0];
    const float bx2v = bx2[0];

    // ================= prologue: fully stage first block =================
    const int bstart = blockIdx.x, bstride = gridDim.x;
    {
        const int b = bstart;
        const float4* hj4 = (const float4*)(hj + (size_t)b * Nn * Dd);
        float4*       o4  = (float4*)(out + OUT_HJ_OFF + (size_t)b * Nn * Dd);
        #pragma unroll
        for (int h = 0; h < 2; h++) {
            float4 v[8];
            #pragma unroll
            for (int i = 0; i < 8; i++) v[i] = hj4[tid + 256 * (h * 8 + i)];
            #pragma unroll
            for (int i = 0; i < 8; i++) split_sts(sm, tid + 256 * (h * 8 + i), v[i], o4);
        }
        if (tid < Dd) smHi[tid] = hi[(size_t)b * Dd + tid];
        if (tid < Cc) smXiV[tid] = xi[(size_t)b * Cc + tid];
        for (int i = tid; i < Nn * Cc; i += 256) smXj[i] = xj[(size_t)b * Nn * Cc + i];
    }
    int p = 0;

    // ================= persistent pipelined loop =================
    for (int b = bstart; b < Bb; b += bstride) {
        const int  bn = b + bstride;
        const bool hn = bn < Bb;
        __syncthreads();   // staged block b visible

        // ---- MMA: warp w owns rows [w*32, w*32+32) ----
        float acc[2][4][4];
        #pragma unroll
        for (int mt = 0; mt < 2; mt++)
            #pragma unroll
            for (int nt = 0; nt < 4; nt++)
                #pragma unroll
                for (int j = 0; j < 4; j++) acc[mt][nt][j] = 0.0f;

        #pragma unroll
        for (int mt = 0; mt < 2; mt++) {
            const int Rm = w * 32 + mt * 16;
            #pragma unroll
            for (int kk = 0; kk < 4; kk++) {
                const uint32_t abyte =
                    swz((uint32_t)((Rm + (lane & 15)) * 128 + kk * 32 + ((lane >> 4) << 4)));
                uint32_t ah0, ah1, ah2, ah3, al0, al1, al2, al3;
                ldm_x4(ah0, ah1, ah2, ah3, aHiAddr + abyte);
                ldm_x4(al0, al1, al2, al3, aLoAddr + abyte);
                #pragma unroll
                for (int nt = 0; nt < 4; nt++) {
                    const uint32_t* blp = smBfrag + ((kk * 4 + nt) * 32 + lane) * 2;
                    uint32_t bl0 = blp[0], bl1 = blp[1];
                    mma_bf16(acc[mt][nt], ah0, ah1, ah2, ah3, BH0[kk][nt], BH1[kk][nt]);
                    mma_bf16(acc[mt][nt], al0, al1, al2, al3, BH0[kk][nt], BH1[kk][nt]);
                    mma_bf16(acc[mt][nt], ah0, ah1, ah2, ah3, bl0, bl1);
                }
            }
        }
        if (w == 1) {   // base[m] + {base, wu0, wu1, wu2}
            float sbase = smBe[lane];
            float s0 = 0.f, s1 = 0.f, s2 = 0.f, s3 = 0.f;
            #pragma unroll
            for (int d = 0; d < Dd; d += 4) {
                s0 += smHi[p * 64 + d + 0] * smWeHi[(d + 0) * Mm + lane];
                s1 += smHi[p * 64 + d + 1] * smWeHi[(d + 1) * Mm + lane];
                s2 += smHi[p * 64 + d + 2] * smWeHi[(d + 2) * Mm + lane];
                s3 += smHi[p * 64 + d + 3] * smWeHi[(d + 3) * Mm + lane];
            }
            sbase += (s0 + s1) + (s2 + s3);
            smBaseC[lane] = make_float4(sbase,
                                        __ldg(&We[(2 * Dd + 0) * Mm + lane]),
                                        __ldg(&We[(2 * Dd + 1) * Mm + lane]),
                                        __ldg(&We[(2 * Dd + 2) * Mm + lane]));
        }
        __syncthreads();   // A smem free; BaseC visible

        // ---- issue next-block batch0 LDGs (overlap with epilogue) ----
        const float4* hj4n = (const float4*)(hj + (size_t)bn * Nn * Dd);
        float4 v0[8];
        if (hn) {
            #pragma unroll
            for (int i = 0; i < 8; i++) v0[i] = hj4n[tid + 256 * i];
        }

        // ---- epilogue ----
        const float xiv0 = smXiV[p * 4 + 0], xiv1 = smXiV[p * 4 + 1], xiv2 = smXiV[p * 4 + 2];
        float micol[8];
        #pragma unroll
        for (int j = 0; j < 8; j++) micol[j] = 0.0f;
        float xa0 = 0.f, xa1 = 0.f, xa2 = 0.f;

        #pragma unroll
        for (int mt = 0; mt < 2; mt++) {
            #pragma unroll
            for (int half = 0; half < 2; half++) {
                const int n = w * 32 + mt * 16 + half * 8 + q;
                const float u0 = xiv0 - smXj[n * 3 + 0];
                const float u1 = xiv1 - smXj[n * 3 + 1];
                const float u2 = xiv2 - smXj[n * 3 + 2];
                const float q0 = u0 * u0, q1 = u1 * u1, q2 = u2 * u2;

                float pr = 0.0f;
                #pragma unroll
                for (int nt = 0; nt < 4; nt++) {
                    const int col = nt * 8 + 2 * s;
                    const float4 b0 = smBaseC[col];
                    const float4 b1 = smBaseC[col + 1];
                    float va = acc[mt][nt][half * 2 + 0] + b0.x + q0 * b0.y + q1 * b0.z + q2 * b0.w;
                    float vb = acc[mt][nt][half * 2 + 1] + b1.x + q0 * b1.y + q1 * b1.z + q2 * b1.w;
                    const float mv0 = silu_f(va);
                    const float mv1 = silu_f(vb);
                    micol[nt * 2 + 0] += mv0;
                    micol[nt * 2 + 1] += mv1;
                    pr += mv0 * wxr_[nt * 2] + mv1 * wxr_[nt * 2 + 1];
                }
                pr += __shfl_xor_sync(0xffffffffu, pr, 1);
                pr += __shfl_xor_sync(0xffffffffu, pr, 2);
                const float px = silu_f(pr + bxv);
                xa0 += u0 * px; xa1 += u1 * px; xa2 += u2 * px;   // 4x redundant per quad
            }
        }
        #pragma unroll
        for (int j = 0; j < 8; j++) {
            micol[j] += __shfl_xor_sync(0xffffffffu, micol[j], 4);
            micol[j] += __shfl_xor_sync(0xffffffffu, micol[j], 8);
            micol[j] += __shfl_xor_sync(0xffffffffu, micol[j], 16);
        }
        if (lane < 4) {
            #pragma unroll
            for (int nt = 0; nt < 4; nt++) {
                smMip[w * 32 + nt * 8 + 2 * lane + 0] = micol[nt * 2 + 0];
                smMip[w * 32 + nt * 8 + 2 * lane + 1] = micol[nt * 2 + 1];
            }
        }
        #pragma unroll
        for (int off = 16; off; off >>= 1) {
            xa0 += __shfl_xor_sync(0xffffffffu, xa0, off);
            xa1 += __shfl_xor_sync(0xffffffffu, xa1, off);
            xa2 += __shfl_xor_sync(0xffffffffu, xa2, off);
        }
        if (lane == 0) { smXa[w*4+0] = xa0; smXa[w*4+1] = xa1; smXa[w*4+2] = xa2; }
        __syncthreads();   // epilogue reads of smXj/BaseC done; smMip/smXa visible

        // ---- store batch0, issue batch1, stage small next-block inputs ----
        float4* o4n = (float4*)(out + OUT_HJ_OFF + (size_t)bn * Nn * Dd);
        float4 v1[8];
        if (hn) {
            #pragma unroll
            for (int i = 0; i < 8; i++) split_sts(sm, tid + 256 * i, v0[i], o4n);
            #pragma unroll
            for (int i = 0; i < 8; i++) v1[i] = hj4n[tid + 256 * (8 + i)];
            if (tid < Dd) smHi[(p ^ 1) * 64 + tid] = hi[(size_t)bn * Dd + tid];
            if (tid < Cc) smXiV[(p ^ 1) * 4 + tid] = xi[(size_t)bn * Cc + tid];
            for (int i = tid; i < Nn * Cc; i += 256) smXj[i] = xj[(size_t)bn * Nn * Cc + i];
        }

        // ---- tail: warp 0 reduce; warps 0-1 final GEMM; others continue ----
        if (w == 0) {
            float mt = 0.0f;
            #pragma unroll
            for (int wi = 0; wi < 8; wi++) mt += smMip[wi * 32 + lane];
            smMif[lane] = mt;
            float v2 = mt * smWx2[lane];
            #pragma unroll
            for (int off = 16; off; off >>= 1)
                v2 += __shfl_xor_sync(0xffffffffu, v2, off);
            const float phi2 = silu_f(v2 + bx2v);
            if (lane < Cc) {
                float xt = 0.0f;
                #pragma unroll
                for (int wi = 0; wi < 8; wi++) xt += smXa[wi * 4 + lane];
                out[OUT_XI_OFF + (size_t)b * Cc + lane] =
                    smXiV[p * 4 + lane] * phi2 + xt * (1.0f / (4.0f * (float)Nn));
            }
        }
        if (w < 2) {
            asm volatile("bar.sync 1, 64;" ::: "memory");   // smMif ready (warps 0-1)
            float a = bh[tid];
            #pragma unroll 8
            for (int d = 0; d < Dd; d++)  a += smHi[p * 64 + d] * smWh[d * Dd + tid];
            #pragma unroll 8
            for (int m = 0; m < Mm; m++)  a += smMif[m] * smWh[(Dd + m) * Dd + tid];
            out[(size_t)b * Dd + tid] = silu_f(a);
        }

        if (hn) {
            #pragma unroll
            for (int i = 0; i < 8; i++) split_sts(sm, tid + 256 * (8 + i), v1[i], o4n);
        }
        p ^= 1;
        // loop-top __syncthreads makes all staging visible
    }
}

extern "C" void kernel_launch(void* const* d_in, const int* in_sizes, int n_in,
                              void* d_out, int out_size) {
    const float* hi  = (const float*)d_in[0];
    const float* xi  = (const float*)d_in[1];
    const float* hj  = (const float*)d_in[2];
    const float* xj  = (const float*)d_in[3];
    const float* We  = (const float*)d_in[4];
    const float* be  = (const float*)d_in[5];
    const float* Wx  = (const float*)d_in[6];
    const float* bx  = (const float*)d_in[7];
    const float* Wx2 = (const float*)d_in[8];
    const float* bx2 = (const float*)d_in[9];
    const float* Wh  = (const float*)d_in[10];
    const float* bh  = (const float*)d_in[11];
    float* out = (float*)d_out;

    cudaMemcpyAsync(out + OUT_XJ_OFF, (const void*)xj,
                    (size_t)Bb * Nn * Cc * sizeof(float),
                    cudaMemcpyDeviceToDevice);

    cudaFuncSetAttribute(e2gn2_kernel,
                         cudaFuncAttributeMaxDynamicSharedMemorySize, SMEM_TOTAL);
    int smCount = 148;
    cudaDeviceGetAttribute(&smCount, cudaDevAttrMultiProcessorCount, 0);
    const int grid = 2 * smCount;

    e2gn2_kernel<<<grid, 256, SMEM_TOTAL>>>(hi, xi, hj, xj, We, be, Wx, bx,
                                            Wx2, bx2, Wh, bh, out);
}

// round 9
// speedup vs baseline: 1.9499x; 1.9499x over previous
#include <cuda_runtime.h>
#include <cstdint>

#define Bb 4096
#define Nn 256
#define Dd 64
#define Cc 3
#define Mm 32

#define OUT_XI_OFF ((size_t)Bb * Dd)
#define OUT_HJ_OFF (OUT_XI_OFF + (size_t)Bb * Cc)
#define OUT_XJ_OFF (OUT_HJ_OFF + (size_t)Bb * Nn * Dd)

// ---- dynamic smem layout (byte offsets) ----
#define SMO_A      0        // 256 x 64 fp32, chunk-rotated = 65536
#define SMO_BF     65536    // B frags: 8kk x 4nt x 32 lanes x 16B = 16384
#define SMO_WH     81920    // 96 x 64 fp32 = 24576
#define SMO_XJ     106496   // 2 x 768 fp32 = 6144 (double buffered)
#define SMO_HI     112640   // 2 x 64 fp32 = 512
#define SMO_BASEC  113152   // 32 x float4 = 512
#define SMO_MIP    113664   // 8 x 32 fp32 = 1024
#define SMO_XA     114688   // 8 x 4 fp32 = 128
#define SMO_MIF    114816   // 32 fp32 = 128
#define SMO_XIV    114944   // 2 x 4 fp32 = 32
#define SMO_SC     114976   // bx, bx2
#define SMEM_TOTAL 114984

#define TF32_MASK 0xFFFFE000u

__device__ __forceinline__ uint32_t smem_u32(const void* p) {
    uint32_t a;
    asm("{ .reg .u64 t; cvta.to.shared.u64 t, %1; cvt.u32.u64 %0, t; }" : "=r"(a) : "l"(p));
    return a;
}
__device__ __forceinline__ float silu_f(float x) {
    float e, r;
    asm("ex2.approx.f32 %0, %1;" : "=f"(e) : "f"(x * -1.442695041f));
    asm("rcp.approx.f32 %0, %1;" : "=f"(r) : "f"(e + 1.0f));
    return x * r;
}
__device__ __forceinline__ void mma_tf32(float* c, uint32_t a0, uint32_t a1,
                                         uint32_t a2, uint32_t a3,
                                         uint32_t b0, uint32_t b1) {
    asm volatile(
        "mma.sync.aligned.m16n8k8.row.col.f32.tf32.tf32.f32 "
        "{%0,%1,%2,%3}, {%4,%5,%6,%7}, {%8,%9}, {%0,%1,%2,%3};"
        : "+f"(c[0]), "+f"(c[1]), "+f"(c[2]), "+f"(c[3])
        : "r"(a0), "r"(a1), "r"(a2), "r"(a3), "r"(b0), "r"(b1));
}
#define CP16(dst, src) asm volatile("cp.async.cg.shared.global [%0], [%1], 16;" :: "r"(dst), "l"(src))
#define CP4(dst, src)  asm volatile("cp.async.ca.shared.global [%0], [%1], 4;"  :: "r"(dst), "l"(src))
#define CPCOMMIT()     asm volatile("cp.async.commit_group;" ::: "memory")
#define CPWAIT0()      asm volatile("cp.async.wait_group 0;" ::: "memory")

__global__ __launch_bounds__(256, 2) void e2gn2_kernel(
    const float* __restrict__ hi, const float* __restrict__ xi,
    const float* __restrict__ hj, const float* __restrict__ xj,
    const float* __restrict__ We, const float* __restrict__ be,
    const float* __restrict__ Wx, const float* __restrict__ bx,
    const float* __restrict__ Wx2, const float* __restrict__ bx2,
    const float* __restrict__ Wh, const float* __restrict__ bh,
    float* __restrict__ out)
{
    extern __shared__ char sm[];

    const int tid  = threadIdx.x;
    const int w    = tid >> 5;
    const int lane = tid & 31;
    const int q    = lane >> 2;   // groupID (row in frag)
    const int s    = lane & 3;    // threadID_in_group (k / col-pair)

    float*  smWh   = (float*)(sm + SMO_WH);
    float*  smXjF  = (float*)(sm + SMO_XJ);
    float*  smHiF  = (float*)(sm + SMO_HI);
    float4* smBaseC= (float4*)(sm + SMO_BASEC);
    float*  smMip  = (float*)(sm + SMO_MIP);
    float*  smXa   = (float*)(sm + SMO_XA);
    float*  smMif  = (float*)(sm + SMO_MIF);
    float*  smXiV  = (float*)(sm + SMO_XIV);
    float*  smSc   = (float*)(sm + SMO_SC);

    const uint32_t smBase = smem_u32(sm);

    // ================= one-time init =================
    if (tid == 0) { smSc[0] = bx[0]; smSc[1] = bx2[0]; }
    for (int i = tid; i < 6144; i += 256) smWh[i] = Wh[i];
    // B frags: thread holds b0=(k=kk*8+t, n=nt*8+g), b1=(k+4, n); store {bh0,bh1,bl0,bl1}
    for (int idx = tid; idx < 8 * 4 * 32; idx += 256) {
        const int kk = idx >> 7, rest = idx & 127;
        const int nt = rest >> 5, l2 = rest & 31;
        const int t2 = l2 & 3, g2 = l2 >> 2;
        const int k0 = kk * 8 + t2, n = nt * 8 + g2;
        float v0 = We[(Dd + k0)     * Mm + n];
        float v1 = We[(Dd + k0 + 4) * Mm + n];
        float h0 = __uint_as_float(__float_as_uint(v0) & TF32_MASK);
        float h1 = __uint_as_float(__float_as_uint(v1) & TF32_MASK);
        *(float4*)(sm + SMO_BF + ((kk * 4 + nt) * 32 + l2) * 16) =
            make_float4(h0, h1, v0 - h0, v1 - h1);
    }
    float wxr_[8];
    #pragma unroll
    for (int nt = 0; nt < 4; nt++) {
        wxr_[nt * 2 + 0] = Wx[nt * 8 + 2 * s + 0];
        wxr_[nt * 2 + 1] = Wx[nt * 8 + 2 * s + 1];
    }
    const float bxv  = bx[0];
    const float bx2v = bx2[0];

    const int bstart = blockIdx.x, bstride = gridDim.x;
    int p = 0;

    // ---- prologue: async-stage first block (A + smalls into p=0) ----
    {
        const float* hjb = hj + (size_t)bstart * Nn * Dd;
        #pragma unroll
        for (int j = 0; j < 16; j++) {
            const int g = tid + 256 * j;
            const int r = g >> 4, ch = g & 15;
            CP16(smBase + SMO_A + r * 256 + (((ch + r) & 15) << 4), hjb + g * 4);
        }
        if (tid < 192) CP16(smBase + SMO_XJ + tid * 16, xj + (size_t)bstart * 768 + tid * 4);
        if (tid < 16)  CP16(smBase + SMO_HI + tid * 16, hi + (size_t)bstart * 64 + tid * 4);
        if (tid < 3)   CP4 (smBase + SMO_XIV + tid * 4, xi + (size_t)bstart * 3 + tid);
    }
    CPCOMMIT();

    // ================= persistent pipelined loop =================
    for (int b = bstart; b < Bb; b += bstride) {
        const int  bn = b + bstride;
        const bool hn = bn < Bb;

        CPWAIT0();
        __syncthreads();   // staged data visible to all

        // ---- hj pass-through STG from smem ----
        {
            float4* o4 = (float4*)(out + OUT_HJ_OFF + (size_t)b * Nn * Dd);
            #pragma unroll
            for (int j = 0; j < 16; j++) {
                const int g = tid + 256 * j;
                const int r = g >> 4, ch = g & 15;
                o4[g] = *(const float4*)(sm + SMO_A + r * 256 + (((ch + r) & 15) << 4));
            }
        }

        // ---- MMA: warp w owns rows [w*32, w*32+32), tf32 3-pass ----
        float acc[2][4][4];
        #pragma unroll
        for (int mt = 0; mt < 2; mt++)
            #pragma unroll
            for (int nt = 0; nt < 4; nt++)
                #pragma unroll
                for (int j = 0; j < 4; j++) acc[mt][nt][j] = 0.0f;

        #pragma unroll
        for (int mt = 0; mt < 2; mt++) {
            const int r0 = w * 32 + mt * 16 + q;   // r0 & 15 == q ; (r0+8) & 15 == q+8
            #pragma unroll
            for (int kk = 0; kk < 8; kk++) {
                // rotation follows the STORE rule: chunk' = (ch + row) & 15
                const int cA0 = (2 * kk +     q)     & 15;   // row r0,   k-part 0
                const int cA2 = (2 * kk + 1 + q)     & 15;   // row r0,   k-part 1
                const int cB0 = (2 * kk +     q + 8) & 15;   // row r0+8, k-part 0
                const int cB2 = (2 * kk + 1 + q + 8) & 15;   // row r0+8, k-part 1
                const float fa0 = *(const float*)(sm + SMO_A + r0 * 256       + cA0 * 16 + s * 4);
                const float fa1 = *(const float*)(sm + SMO_A + (r0 + 8) * 256 + cB0 * 16 + s * 4);
                const float fa2 = *(const float*)(sm + SMO_A + r0 * 256       + cA2 * 16 + s * 4);
                const float fa3 = *(const float*)(sm + SMO_A + (r0 + 8) * 256 + cB2 * 16 + s * 4);
                const uint32_t ah0 = __float_as_uint(fa0) & TF32_MASK;
                const uint32_t ah1 = __float_as_uint(fa1) & TF32_MASK;
                const uint32_t ah2 = __float_as_uint(fa2) & TF32_MASK;
                const uint32_t ah3 = __float_as_uint(fa3) & TF32_MASK;
                const uint32_t al0 = __float_as_uint(fa0 - __uint_as_float(ah0));
                const uint32_t al1 = __float_as_uint(fa1 - __uint_as_float(ah1));
                const uint32_t al2 = __float_as_uint(fa2 - __uint_as_float(ah2));
                const uint32_t al3 = __float_as_uint(fa3 - __uint_as_float(ah3));
                #pragma unroll
                for (int nt = 0; nt < 4; nt++) {
                    const float4 bf = *(const float4*)(sm + SMO_BF +
                                        ((kk * 4 + nt) * 32 + lane) * 16);
                    const uint32_t bh0 = __float_as_uint(bf.x), bh1 = __float_as_uint(bf.y);
                    const uint32_t bl0 = __float_as_uint(bf.z), bl1 = __float_as_uint(bf.w);
                    mma_tf32(acc[mt][nt], ah0, ah1, ah2, ah3, bh0, bh1);
                    mma_tf32(acc[mt][nt], al0, al1, al2, al3, bh0, bh1);
                    mma_tf32(acc[mt][nt], ah0, ah1, ah2, ah3, bl0, bl1);
                }
            }
        }

        // warp 1: base[m] + {base, wu0, wu1, wu2} (We/be via L1-warm global)
        if (w == 1) {
            float s0 = __ldg(&be[lane]), s1 = 0.f, s2 = 0.f, s3 = 0.f;
            #pragma unroll
            for (int d = 0; d < Dd; d += 4) {
                s0 += smHiF[p * 64 + d + 0] * __ldg(&We[(d + 0) * Mm + lane]);
                s1 += smHiF[p * 64 + d + 1] * __ldg(&We[(d + 1) * Mm + lane]);
                s2 += smHiF[p * 64 + d + 2] * __ldg(&We[(d + 2) * Mm + lane]);
                s3 += smHiF[p * 64 + d + 3] * __ldg(&We[(d + 3) * Mm + lane]);
            }
            smBaseC[lane] = make_float4((s0 + s1) + (s2 + s3),
                                        __ldg(&We[(2 * Dd + 0) * Mm + lane]),
                                        __ldg(&We[(2 * Dd + 1) * Mm + lane]),
                                        __ldg(&We[(2 * Dd + 2) * Mm + lane]));
        }
        __syncthreads();   // A fully consumed; BaseC visible

        // ---- issue next block's async stage (latency hidden by epilogue+tail) ----
        if (hn) {
            const float* hjb = hj + (size_t)bn * Nn * Dd;
            #pragma unroll
            for (int j = 0; j < 16; j++) {
                const int g = tid + 256 * j;
                const int r = g >> 4, ch = g & 15;
                CP16(smBase + SMO_A + r * 256 + (((ch + r) & 15) << 4), hjb + g * 4);
            }
            const int pb = p ^ 1;
            if (tid < 192) CP16(smBase + SMO_XJ + pb * 3072 + tid * 16,
                                xj + (size_t)bn * 768 + tid * 4);
            if (tid < 16)  CP16(smBase + SMO_HI + pb * 256 + tid * 16,
                                hi + (size_t)bn * 64 + tid * 4);
            if (tid < 3)   CP4 (smBase + SMO_XIV + pb * 16 + tid * 4,
                                xi + (size_t)bn * 3 + tid);
        }
        CPCOMMIT();

        // ---- epilogue ----
        const float xiv0 = smXiV[p * 4 + 0], xiv1 = smXiV[p * 4 + 1], xiv2 = smXiV[p * 4 + 2];
        const float* xjp = smXjF + p * 768;
        float micol[8];
        #pragma unroll
        for (int j = 0; j < 8; j++) micol[j] = 0.0f;
        float xa0 = 0.f, xa1 = 0.f, xa2 = 0.f;

        #pragma unroll
        for (int mt = 0; mt < 2; mt++) {
            #pragma unroll
            for (int half = 0; half < 2; half++) {
                const int n = w * 32 + mt * 16 + half * 8 + q;
                const float u0 = xiv0 - xjp[n * 3 + 0];
                const float u1 = xiv1 - xjp[n * 3 + 1];
                const float u2 = xiv2 - xjp[n * 3 + 2];
                const float q0 = u0 * u0, q1 = u1 * u1, q2 = u2 * u2;

                float pr = 0.0f;
                #pragma unroll
                for (int nt = 0; nt < 4; nt++) {
                    const int col = nt * 8 + 2 * s;
                    const float4 b0 = smBaseC[col];
                    const float4 b1 = smBaseC[col + 1];
                    float va = acc[mt][nt][half * 2 + 0] + b0.x + q0 * b0.y + q1 * b0.z + q2 * b0.w;
                    float vb = acc[mt][nt][half * 2 + 1] + b1.x + q0 * b1.y + q1 * b1.z + q2 * b1.w;
                    const float mv0 = silu_f(va);
                    const float mv1 = silu_f(vb);
                    micol[nt * 2 + 0] += mv0;
                    micol[nt * 2 + 1] += mv1;
                    pr += mv0 * wxr_[nt * 2] + mv1 * wxr_[nt * 2 + 1];
                }
                pr += __shfl_xor_sync(0xffffffffu, pr, 1);
                pr += __shfl_xor_sync(0xffffffffu, pr, 2);
                const float px = silu_f(pr + bxv);
                xa0 += u0 * px; xa1 += u1 * px; xa2 += u2 * px;   // 4x redundant per quad
            }
        }
        #pragma unroll
        for (int j = 0; j < 8; j++) {
            micol[j] += __shfl_xor_sync(0xffffffffu, micol[j], 4);
            micol[j] += __shfl_xor_sync(0xffffffffu, micol[j], 8);
            micol[j] += __shfl_xor_sync(0xffffffffu, micol[j], 16);
        }
        if (lane < 4) {
            #pragma unroll
            for (int nt = 0; nt < 4; nt++) {
                smMip[w * 32 + nt * 8 + 2 * lane + 0] = micol[nt * 2 + 0];
                smMip[w * 32 + nt * 8 + 2 * lane + 1] = micol[nt * 2 + 1];
            }
        }
        #pragma unroll
        for (int off = 16; off; off >>= 1) {
            xa0 += __shfl_xor_sync(0xffffffffu, xa0, off);
            xa1 += __shfl_xor_sync(0xffffffffu, xa1, off);
            xa2 += __shfl_xor_sync(0xffffffffu, xa2, off);
        }
        if (lane == 0) { smXa[w*4+0] = xa0; smXa[w*4+1] = xa1; smXa[w*4+2] = xa2; }
        __syncthreads();   // smMip/smXa visible

        // ---- tail: warp 0 reduce; warps 0-1 final GEMM; others to loop top ----
        if (w == 0) {
            float mt = 0.0f;
            #pragma unroll
            for (int wi = 0; wi < 8; wi++) mt += smMip[wi * 32 + lane];
            smMif[lane] = mt;
            float v2 = mt * __ldg(&Wx2[lane]);
            #pragma unroll
            for (int off = 16; off; off >>= 1)
                v2 += __shfl_xor_sync(0xffffffffu, v2, off);
            const float phi2 = silu_f(v2 + bx2v);
            if (lane < Cc) {
                float xt = 0.0f;
                #pragma unroll
                for (int wi = 0; wi < 8; wi++) xt += smXa[wi * 4 + lane];
                out[OUT_XI_OFF + (size_t)b * Cc + lane] =
                    smXiV[p * 4 + lane] * phi2 + xt * (1.0f / (4.0f * (float)Nn));
            }
        }
        if (w < 2) {
            asm volatile("bar.sync 1, 64;" ::: "memory");   // smMif ready (warps 0-1)
            float a = __ldg(&bh[tid]);
            #pragma unroll 8
            for (int d = 0; d < Dd; d++)  a += smHiF[p * 64 + d] * smWh[d * Dd + tid];
            #pragma unroll 8
            for (int m = 0; m < Mm; m++)  a += smMif[m] * smWh[(Dd + m) * Dd + tid];
            out[(size_t)b * Dd + tid] = silu_f(a);
        }
        p ^= 1;
        // loop-top CPWAIT0 + __syncthreads completes the pipeline handoff
    }
}

extern "C" void kernel_launch(void* const* d_in, const int* in_sizes, int n_in,
                              void* d_out, int out_size) {
    const float* hi  = (const float*)d_in[0];
    const float* xi  = (const float*)d_in[1];
    const float* hj  = (const float*)d_in[2];
    const float* xj  = (const float*)d_in[3];
    const float* We  = (const float*)d_in[4];
    const float* be  = (const float*)d_in[5];
    const float* Wx  = (const float*)d_in[6];
    const float* bx  = (const float*)d_in[7];
    const float* Wx2 = (const float*)d_in[8];
    const float* bx2 = (const float*)d_in[9];
    const float* Wh  = (const float*)d_in[10];
    const float* bh  = (const float*)d_in[11];
    float* out = (float*)d_out;

    cudaMemcpyAsync(out + OUT_XJ_OFF, (const void*)xj,
                    (size_t)Bb * Nn * Cc * sizeof(float),
                    cudaMemcpyDeviceToDevice);

    cudaFuncSetAttribute(e2gn2_kernel,
                         cudaFuncAttributeMaxDynamicSharedMemorySize, SMEM_TOTAL);
    int smCount = 148;
    cudaDeviceGetAttribute(&smCount, cudaDevAttrMultiProcessorCount, 0);
    const int grid = 2 * smCount;

    e2gn2_kernel<<<grid, 256, SMEM_TOTAL>>>(hi, xi, hj, xj, We, be, Wx, bx,
                                            Wx2, bx2, Wh, bh, out);
}

// round 10
// speedup vs baseline: 2.2553x; 1.1566x over previous
#include <cuda_runtime.h>
#include <cstdint>

#define Bb 4096
#define Nn 256
#define Dd 64
#define Cc 3
#define Mm 32

#define OUT_XI_OFF ((size_t)Bb * Dd)
#define OUT_HJ_OFF (OUT_XI_OFF + (size_t)Bb * Cc)
#define OUT_XJ_OFF (OUT_HJ_OFF + (size_t)Bb * Nn * Dd)

// ---- dynamic smem layout (byte offsets) ----
#define SMO_A      0        // 256 x 64 fp32, chunk-rotated = 65536 (warp-private bands)
#define SMO_BF     65536    // B frags: 8kk x 4nt x 32 lanes x 16B = 16384
#define SMO_WH     81920    // 96 x 64 fp32 = 24576
#define SMO_XJ     106496   // 2 x 768 fp32 = 6144 (double buffered, warp-private slices)
#define SMO_HI     112640   // 2 x 64 fp32 = 512
#define SMO_BASEC  113152   // 32 x float4 = 512
#define SMO_MIP    113664   // 8 x 32 fp32 = 1024
#define SMO_XA     114688   // 8 x 4 fp32 = 128
#define SMO_MIF    114816   // 32 fp32 = 128
#define SMO_XIV    114944   // 2 x 4 fp32 = 32
#define SMEM_TOTAL 114984

#define TF32_MASK 0xFFFFE000u

__device__ __forceinline__ uint32_t smem_u32(const void* p) {
    uint32_t a;
    asm("{ .reg .u64 t; cvta.to.shared.u64 t, %1; cvt.u32.u64 %0, t; }" : "=r"(a) : "l"(p));
    return a;
}
__device__ __forceinline__ float silu_f(float x) {
    float e, r;
    asm("ex2.approx.f32 %0, %1;" : "=f"(e) : "f"(x * -1.442695041f));
    asm("rcp.approx.f32 %0, %1;" : "=f"(r) : "f"(e + 1.0f));
    return x * r;
}
__device__ __forceinline__ void mma_tf32(float* c, uint32_t a0, uint32_t a1,
                                         uint32_t a2, uint32_t a3,
                                         uint32_t b0, uint32_t b1) {
    asm volatile(
        "mma.sync.aligned.m16n8k8.row.col.f32.tf32.tf32.f32 "
        "{%0,%1,%2,%3}, {%4,%5,%6,%7}, {%8,%9}, {%0,%1,%2,%3};"
        : "+f"(c[0]), "+f"(c[1]), "+f"(c[2]), "+f"(c[3])
        : "r"(a0), "r"(a1), "r"(a2), "r"(a3), "r"(b0), "r"(b1));
}
#define CP16(dst, src) asm volatile("cp.async.cg.shared.global [%0], [%1], 16;" :: "r"(dst), "l"(src))
#define CP4(dst, src)  asm volatile("cp.async.ca.shared.global [%0], [%1], 4;"  :: "r"(dst), "l"(src))
#define CPCOMMIT()     asm volatile("cp.async.commit_group;" ::: "memory")
#define CPWAIT0()      asm volatile("cp.async.wait_group 0;" ::: "memory")

__global__ __launch_bounds__(256, 2) void e2gn2_kernel(
    const float* __restrict__ hi, const float* __restrict__ xi,
    const float* __restrict__ hj, const float* __restrict__ xj,
    const float* __restrict__ We, const float* __restrict__ be,
    const float* __restrict__ Wx, const float* __restrict__ bx,
    const float* __restrict__ Wx2, const float* __restrict__ bx2,
    const float* __restrict__ Wh, const float* __restrict__ bh,
    float* __restrict__ out)
{
    extern __shared__ char sm[];

    const int tid  = threadIdx.x;
    const int w    = tid >> 5;
    const int lane = tid & 31;
    const int q    = lane >> 2;   // groupID (row in frag)
    const int s    = lane & 3;    // threadID_in_group

    float*  smWh   = (float*)(sm + SMO_WH);
    float*  smXjF  = (float*)(sm + SMO_XJ);
    float*  smHiF  = (float*)(sm + SMO_HI);
    float4* smBaseC= (float4*)(sm + SMO_BASEC);
    float*  smMip  = (float*)(sm + SMO_MIP);
    float*  smXa   = (float*)(sm + SMO_XA);
    float*  smMif  = (float*)(sm + SMO_MIF);
    float*  smXiV  = (float*)(sm + SMO_XIV);

    const uint32_t smBase = smem_u32(sm);

    // ================= one-time init =================
    for (int i = tid; i < 6144; i += 256) smWh[i] = Wh[i];
    // B frags: thread holds b0=(k=kk*8+t, n=nt*8+g), b1=(k+4, n); {bh0,bh1,bl0,bl1}
    for (int idx = tid; idx < 8 * 4 * 32; idx += 256) {
        const int kk = idx >> 7, rest = idx & 127;
        const int nt = rest >> 5, l2 = rest & 31;
        const int t2 = l2 & 3, g2 = l2 >> 2;
        const int k0 = kk * 8 + t2, n = nt * 8 + g2;
        float v0 = We[(Dd + k0)     * Mm + n];
        float v1 = We[(Dd + k0 + 4) * Mm + n];
        float h0 = __uint_as_float(__float_as_uint(v0) & TF32_MASK);
        float h1 = __uint_as_float(__float_as_uint(v1) & TF32_MASK);
        *(float4*)(sm + SMO_BF + ((kk * 4 + nt) * 32 + l2) * 16) =
            make_float4(h0, h1, v0 - h0, v1 - h1);
    }
    float wxr_[8];
    #pragma unroll
    for (int nt = 0; nt < 4; nt++) {
        wxr_[nt * 2 + 0] = Wx[nt * 8 + 2 * s + 0];
        wxr_[nt * 2 + 1] = Wx[nt * 8 + 2 * s + 1];
    }
    const float bxv  = bx[0];
    const float bx2v = bx2[0];
    __syncthreads();   // BF/WH visible before any MMA/tail

    const int bstart = blockIdx.x, bstride = gridDim.x;
    int p = 0;

    // ---- per-warp staging macro: warp w's A band + xj slice (+ w2: hi, xiv) ----
    #define STAGE_WARP(bsrc, pb) do {                                              \
        const float* hjb_ = hj + (size_t)(bsrc) * Nn * Dd;                         \
        _Pragma("unroll")                                                          \
        for (int j = 0; j < 16; j++) {                                             \
            const int row_ = w * 32 + j * 2 + (lane >> 4);                         \
            const int ch_  = lane & 15;                                            \
            CP16(smBase + SMO_A + row_ * 256 + (((ch_ + row_) & 15) << 4),         \
                 hjb_ + row_ * 64 + ch_ * 4);                                      \
        }                                                                          \
        if (lane < 24) CP16(smBase + SMO_XJ + (pb) * 3072 + w * 384 + lane * 16,   \
                            xj + (size_t)(bsrc) * 768 + w * 96 + lane * 4);        \
        if (w == 2) {                                                              \
            if (lane < 16) CP16(smBase + SMO_HI + (pb) * 256 + lane * 16,          \
                                hi + (size_t)(bsrc) * 64 + lane * 4);              \
            else if (lane < 19) CP4(smBase + SMO_XIV + (pb) * 16 + (lane-16) * 4,  \
                                    xi + (size_t)(bsrc) * 3 + (lane - 16));        \
        }                                                                          \
        CPCOMMIT();                                                                \
    } while (0)

    STAGE_WARP(bstart, 0);   // prologue

    // ================= persistent pipelined loop =================
    for (int b = bstart; b < Bb; b += bstride) {
        const int  bn = b + bstride;
        const bool hn = bn < Bb;

        CPWAIT0();   // per-warp: only THIS warp's band + slice must have landed

        // ---- hj pass-through STG from smem (own band) ----
        {
            float4* o4 = (float4*)(out + OUT_HJ_OFF + (size_t)b * Nn * Dd);
            #pragma unroll
            for (int j = 0; j < 16; j++) {
                const int row = w * 32 + j * 2 + (lane >> 4);
                const int ch  = lane & 15;
                o4[row * 16 + ch] = *(const float4*)(sm + SMO_A + row * 256 +
                                                     (((ch + row) & 15) << 4));
            }
        }

        // ---- MMA: own band rows [w*32, w*32+32), tf32 3-pass ----
        float acc[2][4][4];
        #pragma unroll
        for (int mt = 0; mt < 2; mt++)
            #pragma unroll
            for (int nt = 0; nt < 4; nt++)
                #pragma unroll
                for (int j = 0; j < 4; j++) acc[mt][nt][j] = 0.0f;

        #pragma unroll
        for (int mt = 0; mt < 2; mt++) {
            const int r0 = w * 32 + mt * 16 + q;
            #pragma unroll
            for (int kk = 0; kk < 8; kk++) {
                const int cA0 = (2 * kk +     q)     & 15;
                const int cA2 = (2 * kk + 1 + q)     & 15;
                const int cB0 = (2 * kk +     q + 8) & 15;
                const int cB2 = (2 * kk + 1 + q + 8) & 15;
                const float fa0 = *(const float*)(sm + SMO_A + r0 * 256       + cA0 * 16 + s * 4);
                const float fa1 = *(const float*)(sm + SMO_A + (r0 + 8) * 256 + cB0 * 16 + s * 4);
                const float fa2 = *(const float*)(sm + SMO_A + r0 * 256       + cA2 * 16 + s * 4);
                const float fa3 = *(const float*)(sm + SMO_A + (r0 + 8) * 256 + cB2 * 16 + s * 4);
                const uint32_t ah0 = __float_as_uint(fa0) & TF32_MASK;
                const uint32_t ah1 = __float_as_uint(fa1) & TF32_MASK;
                const uint32_t ah2 = __float_as_uint(fa2) & TF32_MASK;
                const uint32_t ah3 = __float_as_uint(fa3) & TF32_MASK;
                const uint32_t al0 = __float_as_uint(fa0 - __uint_as_float(ah0));
                const uint32_t al1 = __float_as_uint(fa1 - __uint_as_float(ah1));
                const uint32_t al2 = __float_as_uint(fa2 - __uint_as_float(ah2));
                const uint32_t al3 = __float_as_uint(fa3 - __uint_as_float(ah3));
                #pragma unroll
                for (int nt = 0; nt < 4; nt++) {
                    const float4 bf = *(const float4*)(sm + SMO_BF +
                                        ((kk * 4 + nt) * 32 + lane) * 16);
                    const uint32_t bh0 = __float_as_uint(bf.x), bh1 = __float_as_uint(bf.y);
                    const uint32_t bl0 = __float_as_uint(bf.z), bl1 = __float_as_uint(bf.w);
                    mma_tf32(acc[mt][nt], ah0, ah1, ah2, ah3, bh0, bh1);
                    mma_tf32(acc[mt][nt], al0, al1, al2, al3, bh0, bh1);
                    mma_tf32(acc[mt][nt], ah0, ah1, ah2, ah3, bl0, bl1);
                }
            }
        }

        // warp 2: base[m] + {base, wu0, wu1, wu2}  (hi/xiv were its own loads)
        if (w == 2) {
            float s0 = __ldg(&be[lane]), s1 = 0.f, s2 = 0.f, s3 = 0.f;
            #pragma unroll
            for (int d = 0; d < Dd; d += 4) {
                s0 += smHiF[p * 64 + d + 0] * __ldg(&We[(d + 0) * Mm + lane]);
                s1 += smHiF[p * 64 + d + 1] * __ldg(&We[(d + 1) * Mm + lane]);
                s2 += smHiF[p * 64 + d + 2] * __ldg(&We[(d + 2) * Mm + lane]);
                s3 += smHiF[p * 64 + d + 3] * __ldg(&We[(d + 3) * Mm + lane]);
            }
            smBaseC[lane] = make_float4((s0 + s1) + (s2 + s3),
                                        __ldg(&We[(2 * Dd + 0) * Mm + lane]),
                                        __ldg(&We[(2 * Dd + 1) * Mm + lane]),
                                        __ldg(&We[(2 * Dd + 2) * Mm + lane]));
        }

        // ---- own A band consumed: issue next block's stage immediately ----
        if (hn) STAGE_WARP(bn, p ^ 1);
        else    CPCOMMIT();   // keep group count consistent

        __syncthreads();   // barrier(1): BaseC/xiv visible; gates smMip reuse

        // ---- epilogue (u/q precomputed; BaseC loaded once per nt) ----
        const float xiv0 = smXiV[p * 4 + 0], xiv1 = smXiV[p * 4 + 1], xiv2 = smXiV[p * 4 + 2];
        const float* xjp = smXjF + p * 768;
        float u0_[4], u1_[4], u2_[4], q0_[4], q1_[4], q2_[4];
        #pragma unroll
        for (int mh = 0; mh < 4; mh++) {
            const int n = w * 32 + (mh >> 1) * 16 + (mh & 1) * 8 + q;
            u0_[mh] = xiv0 - xjp[n * 3 + 0];
            u1_[mh] = xiv1 - xjp[n * 3 + 1];
            u2_[mh] = xiv2 - xjp[n * 3 + 2];
            q0_[mh] = u0_[mh] * u0_[mh];
            q1_[mh] = u1_[mh] * u1_[mh];
            q2_[mh] = u2_[mh] * u2_[mh];
        }
        float micol[8];
        #pragma unroll
        for (int j = 0; j < 8; j++) micol[j] = 0.0f;
        float pr[4] = {0.f, 0.f, 0.f, 0.f};

        #pragma unroll
        for (int nt = 0; nt < 4; nt++) {
            const int col = nt * 8 + 2 * s;
            const float4 b0 = smBaseC[col];
            const float4 b1 = smBaseC[col + 1];
            #pragma unroll
            for (int mh = 0; mh < 4; mh++) {
                const int mt = mh >> 1, hf = mh & 1;
                float va = acc[mt][nt][hf * 2 + 0] + b0.x + q0_[mh] * b0.y
                         + q1_[mh] * b0.z + q2_[mh] * b0.w;
                float vb = acc[mt][nt][hf * 2 + 1] + b1.x + q0_[mh] * b1.y
                         + q1_[mh] * b1.z + q2_[mh] * b1.w;
                const float mv0 = silu_f(va);
                const float mv1 = silu_f(vb);
                micol[nt * 2 + 0] += mv0;
                micol[nt * 2 + 1] += mv1;
                pr[mh] += mv0 * wxr_[nt * 2 + 0] + mv1 * wxr_[nt * 2 + 1];
            }
        }
        float xa0 = 0.f, xa1 = 0.f, xa2 = 0.f;
        #pragma unroll
        for (int mh = 0; mh < 4; mh++) {
            float prr = pr[mh];
            prr += __shfl_xor_sync(0xffffffffu, prr, 1);
            prr += __shfl_xor_sync(0xffffffffu, prr, 2);
            const float px = silu_f(prr + bxv);
            xa0 += u0_[mh] * px; xa1 += u1_[mh] * px; xa2 += u2_[mh] * px;  // 4x per quad
        }
        #pragma unroll
        for (int j = 0; j < 8; j++) {
            micol[j] += __shfl_xor_sync(0xffffffffu, micol[j], 4);
            micol[j] += __shfl_xor_sync(0xffffffffu, micol[j], 8);
            micol[j] += __shfl_xor_sync(0xffffffffu, micol[j], 16);
        }
        if (lane < 4) {
            #pragma unroll
            for (int nt = 0; nt < 4; nt++) {
                smMip[w * 32 + nt * 8 + 2 * lane + 0] = micol[nt * 2 + 0];
                smMip[w * 32 + nt * 8 + 2 * lane + 1] = micol[nt * 2 + 1];
            }
        }
        #pragma unroll
        for (int off = 16; off; off >>= 1) {
            xa0 += __shfl_xor_sync(0xffffffffu, xa0, off);
            xa1 += __shfl_xor_sync(0xffffffffu, xa1, off);
            xa2 += __shfl_xor_sync(0xffffffffu, xa2, off);
        }
        if (lane == 0) { smXa[w*4+0] = xa0; smXa[w*4+1] = xa1; smXa[w*4+2] = xa2; }

        // ---- barrier(2): split — warps 2-7 arrive and RUN AHEAD; w0/w1 sync ----
        if (w < 2) {
            asm volatile("bar.sync 2, 256;" ::: "memory");
        } else {
            asm volatile("bar.arrive 2, 256;" ::: "memory");
        }

        // ---- tail (w0/w1 only; warps 2-7 already in next iteration) ----
        if (w == 0) {
            float mt = 0.0f;
            #pragma unroll
            for (int wi = 0; wi < 8; wi++) mt += smMip[wi * 32 + lane];
            smMif[lane] = mt;
            float v2 = mt * __ldg(&Wx2[lane]);
            #pragma unroll
            for (int off = 16; off; off >>= 1)
                v2 += __shfl_xor_sync(0xffffffffu, v2, off);
            const float phi2 = silu_f(v2 + bx2v);
            if (lane < Cc) {
                float xt = 0.0f;
                #pragma unroll
                for (int wi = 0; wi < 8; wi++) xt += smXa[wi * 4 + lane];
                out[OUT_XI_OFF + (size_t)b * Cc + lane] =
                    smXiV[p * 4 + lane] * phi2 + xt * (1.0f / (4.0f * (float)Nn));
            }
        }
        if (w < 2) {
            asm volatile("bar.sync 1, 64;" ::: "memory");   // smMif ready
            float a = __ldg(&bh[tid]);
            #pragma unroll 8
            for (int d = 0; d < Dd; d++)  a += smHiF[p * 64 + d] * smWh[d * Dd + tid];
            #pragma unroll 8
            for (int m = 0; m < Mm; m++)  a += smMif[m] * smWh[(Dd + m) * Dd + tid];
            out[(size_t)b * Dd + tid] = silu_f(a);
        }
        p ^= 1;
    }
    #undef STAGE_WARP
}

extern "C" void kernel_launch(void* const* d_in, const int* in_sizes, int n_in,
                              void* d_out, int out_size) {
    const float* hi  = (const float*)d_in[0];
    const float* xi  = (const float*)d_in[1];
    const float* hj  = (const float*)d_in[2];
    const float* xj  = (const float*)d_in[3];
    const float* We  = (const float*)d_in[4];
    const float* be  = (const float*)d_in[5];
    const float* Wx  = (const float*)d_in[6];
    const float* bx  = (const float*)d_in[7];
    const float* Wx2 = (const float*)d_in[8];
    const float* bx2 = (const float*)d_in[9];
    const float* Wh  = (const float*)d_in[10];
    const float* bh  = (const float*)d_in[11];
    float* out = (float*)d_out;

    cudaMemcpyAsync(out + OUT_XJ_OFF, (const void*)xj,
                    (size_t)Bb * Nn * Cc * sizeof(float),
                    cudaMemcpyDeviceToDevice);

    cudaFuncSetAttribute(e2gn2_kernel,
                         cudaFuncAttributeMaxDynamicSharedMemorySize, SMEM_TOTAL);
    int smCount = 148;
    cudaDeviceGetAttribute(&smCount, cudaDevAttrMultiProcessorCount, 0);
    const int grid = 2 * smCount;

    e2gn2_kernel<<<grid, 256, SMEM_TOTAL>>>(hi, xi, hj, xj, We, be, Wx, bx,
                                            Wx2, bx2, Wh, bh, out);
}

// round 11
// speedup vs baseline: 2.4756x; 1.0977x over previous
#include <cuda_runtime.h>
#include <cstdint>

#define Bb 4096
#define Nn 256
#define Dd 64
#define Cc 3
#define Mm 32

#define OUT_XI_OFF ((size_t)Bb * Dd)
#define OUT_HJ_OFF (OUT_XI_OFF + (size_t)Bb * Cc)
#define OUT_XJ_OFF (OUT_HJ_OFF + (size_t)Bb * Nn * Dd)

// ---- dynamic smem layout (byte offsets) ----
#define SMO_A      0        // 256 x 64 fp32, chunk-rotated = 65536 (warp-private bands)
#define SMO_BF     65536    // B frags (tf32-rounded): 8kk x 4nt x 32 lanes x 8B = 8192
#define SMO_WH     73728    // 96 x 64 fp32 = 24576
#define SMO_XJ     98304    // 2 x 768 fp32 = 6144 (double buffered, warp-private slices)
#define SMO_HI     104448   // 2 x 64 fp32 = 512
#define SMO_BASEC  104960   // 32 x float4 = 512
#define SMO_MIP    105472   // 8 x 32 fp32 = 1024
#define SMO_XA     106496   // 8 x 4 fp32 = 128
#define SMO_MIF    106624   // 32 fp32 = 128
#define SMO_XIV    106752   // 2 x 4 fp32 = 32
#define SMEM_TOTAL 106784

__device__ __forceinline__ uint32_t smem_u32(const void* p) {
    uint32_t a;
    asm("{ .reg .u64 t; cvta.to.shared.u64 t, %1; cvt.u32.u64 %0, t; }" : "=r"(a) : "l"(p));
    return a;
}
__device__ __forceinline__ float silu_f(float x) {
    float e, r;
    asm("ex2.approx.f32 %0, %1;" : "=f"(e) : "f"(x * -1.442695041f));
    asm("rcp.approx.f32 %0, %1;" : "=f"(r) : "f"(e + 1.0f));
    return x * r;
}
__device__ __forceinline__ uint32_t to_tf32(float f) {
    uint32_t u;
    asm("cvt.rna.tf32.f32 %0, %1;" : "=r"(u) : "f"(f));
    return u;
}
__device__ __forceinline__ void mma_tf32(float* c, uint32_t a0, uint32_t a1,
                                         uint32_t a2, uint32_t a3,
                                         uint32_t b0, uint32_t b1) {
    asm volatile(
        "mma.sync.aligned.m16n8k8.row.col.f32.tf32.tf32.f32 "
        "{%0,%1,%2,%3}, {%4,%5,%6,%7}, {%8,%9}, {%0,%1,%2,%3};"
        : "+f"(c[0]), "+f"(c[1]), "+f"(c[2]), "+f"(c[3])
        : "r"(a0), "r"(a1), "r"(a2), "r"(a3), "r"(b0), "r"(b1));
}
#define CP16(dst, src) asm volatile("cp.async.cg.shared.global [%0], [%1], 16;" :: "r"(dst), "l"(src))
#define CP4(dst, src)  asm volatile("cp.async.ca.shared.global [%0], [%1], 4;"  :: "r"(dst), "l"(src))
#define CPCOMMIT()     asm volatile("cp.async.commit_group;" ::: "memory")
#define CPWAIT0()      asm volatile("cp.async.wait_group 0;" ::: "memory")

__global__ __launch_bounds__(256, 2) void e2gn2_kernel(
    const float* __restrict__ hi, const float* __restrict__ xi,
    const float* __restrict__ hj, const float* __restrict__ xj,
    const float* __restrict__ We, const float* __restrict__ be,
    const float* __restrict__ Wx, const float* __restrict__ bx,
    const float* __restrict__ Wx2, const float* __restrict__ bx2,
    const float* __restrict__ Wh, const float* __restrict__ bh,
    float* __restrict__ out)
{
    extern __shared__ char sm[];

    const int tid  = threadIdx.x;
    const int w    = tid >> 5;
    const int lane = tid & 31;
    const int q    = lane >> 2;   // groupID (row in frag)
    const int s    = lane & 3;    // threadID_in_group

    float*  smWh   = (float*)(sm + SMO_WH);
    float*  smXjF  = (float*)(sm + SMO_XJ);
    float*  smHiF  = (float*)(sm + SMO_HI);
    float4* smBaseC= (float4*)(sm + SMO_BASEC);
    float*  smMip  = (float*)(sm + SMO_MIP);
    float*  smXa   = (float*)(sm + SMO_XA);
    float*  smMif  = (float*)(sm + SMO_MIF);
    float*  smXiV  = (float*)(sm + SMO_XIV);

    const uint32_t smBase = smem_u32(sm);

    // ================= one-time init =================
    for (int i = tid; i < 6144; i += 256) smWh[i] = Wh[i];
    // B frags (RN-rounded tf32): thread holds b0=(k=kk*8+t, n=nt*8+g), b1=(k+4, n)
    for (int idx = tid; idx < 8 * 4 * 32; idx += 256) {
        const int kk = idx >> 7, rest = idx & 127;
        const int nt = rest >> 5, l2 = rest & 31;
        const int t2 = l2 & 3, g2 = l2 >> 2;
        const int k0 = kk * 8 + t2, n = nt * 8 + g2;
        uint2 bfr;
        bfr.x = to_tf32(We[(Dd + k0)     * Mm + n]);
        bfr.y = to_tf32(We[(Dd + k0 + 4) * Mm + n]);
        *(uint2*)(sm + SMO_BF + ((kk * 4 + nt) * 32 + l2) * 8) = bfr;
    }
    float wxr_[8];
    #pragma unroll
    for (int nt = 0; nt < 4; nt++) {
        wxr_[nt * 2 + 0] = Wx[nt * 8 + 2 * s + 0];
        wxr_[nt * 2 + 1] = Wx[nt * 8 + 2 * s + 1];
    }
    const float bxv  = bx[0];
    const float bx2v = bx2[0];
    __syncthreads();   // BF/WH visible before any MMA/tail

    const int bstart = blockIdx.x, bstride = gridDim.x;
    int p = 0;

    // ---- per-warp staging: warp w's A band + xj slice (+ w2: hi, xiv) ----
    #define STAGE_WARP(bsrc, pb) do {                                              \
        const float* hjb_ = hj + (size_t)(bsrc) * Nn * Dd;                         \
        _Pragma("unroll")                                                          \
        for (int j = 0; j < 16; j++) {                                             \
            const int row_ = w * 32 + j * 2 + (lane >> 4);                         \
            const int ch_  = lane & 15;                                            \
            CP16(smBase + SMO_A + row_ * 256 + (((ch_ + row_) & 15) << 4),         \
                 hjb_ + row_ * 64 + ch_ * 4);                                      \
        }                                                                          \
        if (lane < 24) CP16(smBase + SMO_XJ + (pb) * 3072 + w * 384 + lane * 16,   \
                            xj + (size_t)(bsrc) * 768 + w * 96 + lane * 4);        \
        if (w == 2) {                                                              \
            if (lane < 16) CP16(smBase + SMO_HI + (pb) * 256 + lane * 16,          \
                                hi + (size_t)(bsrc) * 64 + lane * 4);              \
            else if (lane < 19) CP4(smBase + SMO_XIV + (pb) * 16 + (lane-16) * 4,  \
                                    xi + (size_t)(bsrc) * 3 + (lane - 16));        \
        }                                                                          \
        CPCOMMIT();                                                                \
    } while (0)

    STAGE_WARP(bstart, 0);   // prologue

    // ================= persistent pipelined loop =================
    for (int b = bstart; b < Bb; b += bstride) {
        const int  bn = b + bstride;
        const bool hn = bn < Bb;

        CPWAIT0();   // per-warp: only THIS warp's band + slice must have landed

        // ---- hj + xj pass-through STG from smem (own band / slice) ----
        {
            float4* o4 = (float4*)(out + OUT_HJ_OFF + (size_t)b * Nn * Dd);
            #pragma unroll
            for (int j = 0; j < 16; j++) {
                const int row = w * 32 + j * 2 + (lane >> 4);
                const int ch  = lane & 15;
                o4[row * 16 + ch] = *(const float4*)(sm + SMO_A + row * 256 +
                                                     (((ch + row) & 15) << 4));
            }
            if (lane < 24) {
                float4* oxj = (float4*)(out + OUT_XJ_OFF + (size_t)b * 768);
                oxj[w * 24 + lane] =
                    *(const float4*)(sm + SMO_XJ + p * 3072 + w * 384 + lane * 16);
            }
        }

        // ---- MMA: own band rows [w*32, w*32+32), single-pass RN tf32 ----
        float acc[2][4][4];
        #pragma unroll
        for (int mt = 0; mt < 2; mt++)
            #pragma unroll
            for (int nt = 0; nt < 4; nt++)
                #pragma unroll
                for (int j = 0; j < 4; j++) acc[mt][nt][j] = 0.0f;

        #pragma unroll
        for (int mt = 0; mt < 2; mt++) {
            const int r0 = w * 32 + mt * 16 + q;
            #pragma unroll
            for (int kk = 0; kk < 8; kk++) {
                const int cA0 = (2 * kk +     q)     & 15;
                const int cA2 = (2 * kk + 1 + q)     & 15;
                const int cB0 = (2 * kk +     q + 8) & 15;
                const int cB2 = (2 * kk + 1 + q + 8) & 15;
                const float fa0 = *(const float*)(sm + SMO_A + r0 * 256       + cA0 * 16 + s * 4);
                const float fa1 = *(const float*)(sm + SMO_A + (r0 + 8) * 256 + cB0 * 16 + s * 4);
                const float fa2 = *(const float*)(sm + SMO_A + r0 * 256       + cA2 * 16 + s * 4);
                const float fa3 = *(const float*)(sm + SMO_A + (r0 + 8) * 256 + cB2 * 16 + s * 4);
                const uint32_t a0 = to_tf32(fa0);
                const uint32_t a1 = to_tf32(fa1);
                const uint32_t a2 = to_tf32(fa2);
                const uint32_t a3 = to_tf32(fa3);
                #pragma unroll
                for (int nt = 0; nt < 4; nt++) {
                    const uint2 bf = *(const uint2*)(sm + SMO_BF +
                                        ((kk * 4 + nt) * 32 + lane) * 8);
                    mma_tf32(acc[mt][nt], a0, a1, a2, a3, bf.x, bf.y);
                }
            }
        }

        // warp 2: base[m] + {base, wu0, wu1, wu2}  (hi/xiv were its own loads)
        if (w == 2) {
            float s0 = __ldg(&be[lane]), s1 = 0.f, s2 = 0.f, s3 = 0.f;
            #pragma unroll
            for (int d = 0; d < Dd; d += 4) {
                s0 += smHiF[p * 64 + d + 0] * __ldg(&We[(d + 0) * Mm + lane]);
                s1 += smHiF[p * 64 + d + 1] * __ldg(&We[(d + 1) * Mm + lane]);
                s2 += smHiF[p * 64 + d + 2] * __ldg(&We[(d + 2) * Mm + lane]);
                s3 += smHiF[p * 64 + d + 3] * __ldg(&We[(d + 3) * Mm + lane]);
            }
            smBaseC[lane] = make_float4((s0 + s1) + (s2 + s3),
                                        __ldg(&We[(2 * Dd + 0) * Mm + lane]),
                                        __ldg(&We[(2 * Dd + 1) * Mm + lane]),
                                        __ldg(&We[(2 * Dd + 2) * Mm + lane]));
        }

        // ---- own A band consumed: issue next block's stage immediately ----
        if (hn) STAGE_WARP(bn, p ^ 1);
        else    CPCOMMIT();   // keep group count consistent

        __syncthreads();   // barrier(1): BaseC/xiv visible; gates smMip reuse

        // ---- epilogue ----
        const float xiv0 = smXiV[p * 4 + 0], xiv1 = smXiV[p * 4 + 1], xiv2 = smXiV[p * 4 + 2];
        const float* xjp = smXjF + p * 768;
        float u0_[4], u1_[4], u2_[4], q0_[4], q1_[4], q2_[4];
        #pragma unroll
        for (int mh = 0; mh < 4; mh++) {
            const int n = w * 32 + (mh >> 1) * 16 + (mh & 1) * 8 + q;
            u0_[mh] = xiv0 - xjp[n * 3 + 0];
            u1_[mh] = xiv1 - xjp[n * 3 + 1];
            u2_[mh] = xiv2 - xjp[n * 3 + 2];
            q0_[mh] = u0_[mh] * u0_[mh];
            q1_[mh] = u1_[mh] * u1_[mh];
            q2_[mh] = u2_[mh] * u2_[mh];
        }
        float micol[8];
        #pragma unroll
        for (int j = 0; j < 8; j++) micol[j] = 0.0f;
        float pr[4] = {0.f, 0.f, 0.f, 0.f};

        #pragma unroll
        for (int nt = 0; nt < 4; nt++) {
            const int col = nt * 8 + 2 * s;
            const float4 b0 = smBaseC[col];
            const float4 b1 = smBaseC[col + 1];
            #pragma unroll
            for (int mh = 0; mh < 4; mh++) {
                const int mt = mh >> 1, hf = mh & 1;
                float va = acc[mt][nt][hf * 2 + 0] + b0.x + q0_[mh] * b0.y
                         + q1_[mh] * b0.z + q2_[mh] * b0.w;
                float vb = acc[mt][nt][hf * 2 + 1] + b1.x + q0_[mh] * b1.y
                         + q1_[mh] * b1.z + q2_[mh] * b1.w;
                const float mv0 = silu_f(va);
                const float mv1 = silu_f(vb);
                micol[nt * 2 + 0] += mv0;
                micol[nt * 2 + 1] += mv1;
                pr[mh] += mv0 * wxr_[nt * 2 + 0] + mv1 * wxr_[nt * 2 + 1];
            }
        }
        float xa0 = 0.f, xa1 = 0.f, xa2 = 0.f;
        #pragma unroll
        for (int mh = 0; mh < 4; mh++) {
            float prr = pr[mh];
            prr += __shfl_xor_sync(0xffffffffu, prr, 1);
            prr += __shfl_xor_sync(0xffffffffu, prr, 2);
            const float px = silu_f(prr + bxv);
            xa0 += u0_[mh] * px; xa1 += u1_[mh] * px; xa2 += u2_[mh] * px;  // 4x per quad
        }
        #pragma unroll
        for (int j = 0; j < 8; j++) {
            micol[j] += __shfl_xor_sync(0xffffffffu, micol[j], 4);
            micol[j] += __shfl_xor_sync(0xffffffffu, micol[j], 8);
            micol[j] += __shfl_xor_sync(0xffffffffu, micol[j], 16);
        }
        if (lane < 4) {
            #pragma unroll
            for (int nt = 0; nt < 4; nt++) {
                smMip[w * 32 + nt * 8 + 2 * lane + 0] = micol[nt * 2 + 0];
                smMip[w * 32 + nt * 8 + 2 * lane + 1] = micol[nt * 2 + 1];
            }
        }
        #pragma unroll
        for (int off = 16; off; off >>= 1) {
            xa0 += __shfl_xor_sync(0xffffffffu, xa0, off);
            xa1 += __shfl_xor_sync(0xffffffffu, xa1, off);
            xa2 += __shfl_xor_sync(0xffffffffu, xa2, off);
        }
        if (lane == 0) { smXa[w*4+0] = xa0; smXa[w*4+1] = xa1; smXa[w*4+2] = xa2; }

        // ---- barrier(2): split — warps 2-7 arrive and RUN AHEAD; w0/w1 sync ----
        if (w < 2) {
            asm volatile("bar.sync 2, 256;" ::: "memory");
        } else {
            asm volatile("bar.arrive 2, 256;" ::: "memory");
        }

        // ---- tail (w0/w1 only; warps 2-7 already in next iteration) ----
        if (w == 0) {
            float mt = 0.0f;
            #pragma unroll
            for (int wi = 0; wi < 8; wi++) mt += smMip[wi * 32 + lane];
            smMif[lane] = mt;
            float v2 = mt * __ldg(&Wx2[lane]);
            #pragma unroll
            for (int off = 16; off; off >>= 1)
                v2 += __shfl_xor_sync(0xffffffffu, v2, off);
            const float phi2 = silu_f(v2 + bx2v);
            if (lane < Cc) {
                float xt = 0.0f;
                #pragma unroll
                for (int wi = 0; wi < 8; wi++) xt += smXa[wi * 4 + lane];
                out[OUT_XI_OFF + (size_t)b * Cc + lane] =
                    smXiV[p * 4 + lane] * phi2 + xt * (1.0f / (4.0f * (float)Nn));
            }
        }
        if (w < 2) {
            asm volatile("bar.sync 1, 64;" ::: "memory");   // smMif ready
            float a = __ldg(&bh[tid]);
            #pragma unroll 8
            for (int d = 0; d < Dd; d++)  a += smHiF[p * 64 + d] * smWh[d * Dd + tid];
            #pragma unroll 8
            for (int m = 0; m < Mm; m++)  a += smMif[m] * smWh[(Dd + m) * Dd + tid];
            out[(size_t)b * Dd + tid] = silu_f(a);
        }
        p ^= 1;
    }
    #undef STAGE_WARP
}

extern "C" void kernel_launch(void* const* d_in, const int* in_sizes, int n_in,
                              void* d_out, int out_size) {
    const float* hi  = (const float*)d_in[0];
    const float* xi  = (const float*)d_in[1];
    const float* hj  = (const float*)d_in[2];
    const float* xj  = (const float*)d_in[3];
    const float* We  = (const float*)d_in[4];
    const float* be  = (const float*)d_in[5];
    const float* Wx  = (const float*)d_in[6];
    const float* bx  = (const float*)d_in[7];
    const float* Wx2 = (const float*)d_in[8];
    const float* bx2 = (const float*)d_in[9];
    const float* Wh  = (const float*)d_in[10];
    const float* bh  = (const float*)d_in[11];
    float* out = (float*)d_out;

    cudaFuncSetAttribute(e2gn2_kernel,
                         cudaFuncAttributeMaxDynamicSharedMemorySize, SMEM_TOTAL);
    int smCount = 148;
    cudaDeviceGetAttribute(&smCount, cudaDevAttrMultiProcessorCount, 0);
    const int grid = 2 * smCount;

    e2gn2_kernel<<<grid, 256, SMEM_TOTAL>>>(hi, xi, hj, xj, We, be, Wx, bx,
                                            Wx2, bx2, Wh, bh, out);
}